// round 4
// baseline (speedup 1.0000x reference)
#include <cuda_runtime.h>
#include <cuda_bf16.h>
#include <math.h>

// Problem constants
#define BB 32
#define TT 512
#define DD 300
#define DPAD 304              // padded hidden dim (8*38) for uniform unrolled loop
#define UU 300
#define ZZ 1200               // 4*U
#define MM (BB*TT)            // 16384
#define NTOT (2*ZZ)           // 2400
#define NT 3                  // output classes

// Recurrent kernel partition
#define RBLK 75               // blocks per direction
#define RUNITS 4              // units per block (75*4 = 300)
#define RTHREADS 256

// -------- persistent device scratch (no allocations allowed) --------
__device__ float g_zx[(size_t)2 * MM * ZZ];      // [dir][row(b*T+t)][z]
__device__ float g_hout[(size_t)2 * MM * UU];    // [dir][row][u]
__device__ float g_hstate[4 * UU * BB];          // [parity][dir][u*32+b]
__device__ unsigned int g_bar[2];

// ---------------------------------------------------------------
__global__ void init_kernel() {
    int i = blockIdx.x * blockDim.x + threadIdx.x;
    if (i < 2) g_bar[i] = 0u;
    for (int j = i; j < 4 * UU * BB; j += gridDim.x * blockDim.x)
        g_hstate[j] = 0.0f;
}

// ---------------------------------------------------------------
// zx GEMM: zx[dir][b*T+t][z] = emb[inputs[b,t]] @ Wk_dir + b_dir
// 128x128x8 tile, 256 threads, 8x8 register tile, double-buffered
// ---------------------------------------------------------------
#define GBM 128
#define GBN 128
#define GBK 8

__global__ void __launch_bounds__(256)
zx_gemm(const int* __restrict__ tokens,
        const float* __restrict__ emb,
        const float* __restrict__ Wkf, const float* __restrict__ Wkb,
        const float* __restrict__ bf,  const float* __restrict__ bb)
{
    __shared__ float As[GBK][GBM];
    __shared__ float Bs[GBK][GBN];

    const int tid = threadIdx.x;
    const int m0 = blockIdx.y * GBM;
    const int n0 = blockIdx.x * GBN;

    // A loader mapping: one float4 per thread per k-tile
    const int a_row = tid >> 1;             // 0..127
    const int a_kq  = (tid & 1) * 4;        // 0 or 4
    const int token = tokens[m0 + a_row];
    const float* arow = emb + (size_t)token * DD;

    // B loader mapping
    const int b_k = tid >> 5;               // 0..7
    const int b_n = (tid & 31) * 4;         // 0..124
    const int ng  = n0 + b_n;
    const int bdir = (ng >= ZZ) ? 1 : 0;
    const float* Wk = bdir ? Wkb : Wkf;
    const int ncol = ng - bdir * ZZ;
    const bool nvalid = (ng < NTOT);

    const int tx = tid & 15;
    const int ty = tid >> 4;

    float acc[8][8];
    #pragma unroll
    for (int i = 0; i < 8; ++i)
        #pragma unroll
        for (int j = 0; j < 8; ++j) acc[i][j] = 0.0f;

    // prefetch tile k0 = 0
    float4 av = make_float4(0.f, 0.f, 0.f, 0.f);
    if (a_kq + 3 < DD) av = *(const float4*)(arow + a_kq);
    float4 bv = make_float4(0.f, 0.f, 0.f, 0.f);
    if (b_k < DD && nvalid) bv = *(const float4*)(Wk + (size_t)b_k * ZZ + ncol);

    for (int k0 = 0; k0 < DD; k0 += GBK) {
        As[a_kq + 0][a_row] = av.x;
        As[a_kq + 1][a_row] = av.y;
        As[a_kq + 2][a_row] = av.z;
        As[a_kq + 3][a_row] = av.w;
        *(float4*)&Bs[b_k][b_n] = bv;
        __syncthreads();

        // prefetch next tile during compute
        int kn = k0 + GBK;
        av = make_float4(0.f, 0.f, 0.f, 0.f);
        bv = make_float4(0.f, 0.f, 0.f, 0.f);
        if (kn < DD) {
            int k = kn + a_kq;
            if (k + 3 < DD) av = *(const float4*)(arow + k);
            int kb = kn + b_k;
            if (kb < DD && nvalid)
                bv = *(const float4*)(Wk + (size_t)kb * ZZ + ncol);
        }

        #pragma unroll
        for (int kk = 0; kk < GBK; ++kk) {
            float4 a0 = *(float4*)&As[kk][ty * 8];
            float4 a1 = *(float4*)&As[kk][ty * 8 + 4];
            float4 b0 = *(float4*)&Bs[kk][tx * 8];
            float4 b1 = *(float4*)&Bs[kk][tx * 8 + 4];
            float af[8] = {a0.x, a0.y, a0.z, a0.w, a1.x, a1.y, a1.z, a1.w};
            float bfr[8] = {b0.x, b0.y, b0.z, b0.w, b1.x, b1.y, b1.z, b1.w};
            #pragma unroll
            for (int i = 0; i < 8; ++i)
                #pragma unroll
                for (int j = 0; j < 8; ++j)
                    acc[i][j] += af[i] * bfr[j];
        }
        __syncthreads();
    }

    // epilogue: add bias, scatter to per-direction zx buffers
    #pragma unroll
    for (int i = 0; i < 8; ++i) {
        int m = m0 + ty * 8 + i;
        #pragma unroll
        for (int j = 0; j < 8; ++j) {
            int n = n0 + tx * 8 + j;
            if (n < NTOT) {
                int dir = (n >= ZZ) ? 1 : 0;
                int zc = n - dir * ZZ;
                float bias = dir ? bb[zc] : bf[zc];
                g_zx[(size_t)dir * MM * ZZ + (size_t)m * ZZ + zc] = acc[i][j] + bias;
            }
        }
    }
}

// ---------------------------------------------------------------
// Persistent recurrent kernel. 150 blocks (75/dir), 256 threads,
// 1 block/SM. Wr slice lives in REGISTERS (38 float4 per thread)
// for all 512 steps; h exchanged via double-buffered global state
// + per-direction barrier (atomic arrive, volatile-load poll).
// ---------------------------------------------------------------
__device__ __forceinline__ float sigf(float x) {
    return 1.0f / (1.0f + __expf(-x));
}
__device__ __forceinline__ float tanhfast(float x) {
    // tanh(x) = 2*sigmoid(2x) - 1, via MUFU ex2 path
    return 2.0f / (1.0f + __expf(-2.0f * x)) - 1.0f;
}

__global__ void __launch_bounds__(RTHREADS, 1)
lstm_rec(const float* __restrict__ Wrf, const float* __restrict__ Wrb,
         const int* __restrict__ seqlen)
{
    extern __shared__ float smem[];
    float* w_sh  = smem;                        // DPAD*16 = 4864 (staging only)
    float* h_sh  = smem + DPAD * 16;            // DPAD*32 = 9728
    float* red   = smem + DPAD * 16 + DPAD * 32;  // 8*32*16 = 4096
    float* zx_sh = red + 4096;                  // 512

    const int tid  = threadIdx.x;
    const int dir  = blockIdx.x / RBLK;
    const int blk  = blockIdx.x % RBLK;
    const int u0   = blk * RUNITS;

    const float* Wr  = dir ? Wrb : Wrf;
    const float* zxd = g_zx + (size_t)dir * MM * ZZ;

    // stage Wr slice into smem (zero-padded d >= 300):
    // w_sh[d*16 + ul*4 + g] = Wr[d][g*300 + u0+ul]
    for (int i = tid; i < DPAD * 16; i += RTHREADS) {
        int d  = i >> 4;
        int ul = (i >> 2) & 3;
        int gg = i & 3;
        w_sh[i] = (d < DD) ? Wr[(size_t)d * ZZ + gg * UU + u0 + ul] : 0.0f;
    }
    // zero the h pad region once (d = 300..303, never rewritten)
    for (int i = DD * 32 + tid; i < DPAD * 32; i += RTHREADS) h_sh[i] = 0.0f;
    __syncthreads();

    const int ds   = tid >> 5;      // d-slice 0..7
    const int cell = tid & 31;
    const int ul   = cell >> 3;     // unit 0..3
    const int bq   = cell & 7;      // batch quad 0..7

    // copy this thread's Wr column slice to registers (38 float4 = 152 regs)
    float4 w_reg[38];
    {
        const float4* w4s = (const float4*)w_sh;
        #pragma unroll
        for (int it = 0; it < 38; ++it)
            w_reg[it] = w4s[(ds + 8 * it) * 4 + ul];
    }

    // finisher state (threads 0..127 each own one (b,u) cell)
    float cF = 0.0f, hF = 0.0f;
    int uF = 0, bF = 0, slen = 0;
    if (tid < 128) {
        int cf = tid >> 2, bl = tid & 3;
        uF = u0 + (cf >> 3);
        bF = (cf & 7) * 4 + bl;
        slen = seqlen[bF];
    }
    __syncthreads();

    unsigned int* bar = &g_bar[dir];
    const float4* h4 = (const float4*)h_sh;
    float4* r4  = (float4*)red;
    float4* zs4 = (float4*)zx_sh;

    for (int step = 0; step < TT; ++step) {
        const int t = dir ? (TT - 1 - step) : step;

        // prefetch this step's zx tile
        float4 zv = make_float4(0.f, 0.f, 0.f, 0.f);
        if (tid < 128) {
            int b  = tid >> 2;
            int gg = tid & 3;
            zv = *(const float4*)(zxd + ((size_t)b * TT + t) * ZZ + gg * UU + u0);
        }

        // reload h (written by all blocks of this dir last step) — bypass L1
        {
            const float4* hin =
                (const float4*)(g_hstate + ((step & 1) * 2 + dir) * UU * BB);
            float4* hsh4 = (float4*)h_sh;
            for (int i = tid; i < (UU * BB) / 4; i += RTHREADS)
                hsh4[i] = __ldcg(hin + i);
        }
        __syncthreads();

        // partial dots over d-slice {ds, ds+8, ...}, w from registers
        float acc[4][4];
        #pragma unroll
        for (int g = 0; g < 4; ++g)
            #pragma unroll
            for (int b = 0; b < 4; ++b) acc[g][b] = 0.0f;

        #pragma unroll
        for (int it = 0; it < 38; ++it) {
            float4 w = w_reg[it];
            float4 h = h4[(ds + 8 * it) * 8 + bq];
            acc[0][0] += w.x * h.x; acc[0][1] += w.x * h.y; acc[0][2] += w.x * h.z; acc[0][3] += w.x * h.w;
            acc[1][0] += w.y * h.x; acc[1][1] += w.y * h.y; acc[1][2] += w.y * h.z; acc[1][3] += w.y * h.w;
            acc[2][0] += w.z * h.x; acc[2][1] += w.z * h.y; acc[2][2] += w.z * h.z; acc[2][3] += w.z * h.w;
            acc[3][0] += w.w * h.x; acc[3][1] += w.w * h.y; acc[3][2] += w.w * h.z; acc[3][3] += w.w * h.w;
        }

        // spill partials + staged zx
        {
            int rb = ds * 128 + cell * 4;   // float4 units
            r4[rb + 0] = make_float4(acc[0][0], acc[0][1], acc[0][2], acc[0][3]);
            r4[rb + 1] = make_float4(acc[1][0], acc[1][1], acc[1][2], acc[1][3]);
            r4[rb + 2] = make_float4(acc[2][0], acc[2][1], acc[2][2], acc[2][3]);
            r4[rb + 3] = make_float4(acc[3][0], acc[3][1], acc[3][2], acc[3][3]);
        }
        if (tid < 128) zs4[tid] = zv;
        __syncthreads();

        // finish: reduce 8 slices, gates, state update, store h-state
        if (tid < 128) {
            int cf = tid >> 2, bl = tid & 3;
            float zi = zx_sh[(bF * 4 + 0) * 4 + (uF - u0)];
            float zf = zx_sh[(bF * 4 + 1) * 4 + (uF - u0)];
            float zg = zx_sh[(bF * 4 + 2) * 4 + (uF - u0)];
            float zo = zx_sh[(bF * 4 + 3) * 4 + (uF - u0)];
            #pragma unroll
            for (int s = 0; s < 8; ++s) {
                const float* rr = red + s * 512 + cf * 16 + bl;
                zi += rr[0]; zf += rr[4]; zg += rr[8]; zo += rr[12];
            }
            float ig = sigf(zi);
            float fg = sigf(zf);
            float gg = tanhfast(zg);
            float og = sigf(zo);
            float cn = fg * cF + ig * gg;
            float hn = og * tanhfast(cn);
            if (t < slen) { cF = cn; hF = hn; }
            float* hw = g_hstate + (((step + 1) & 1) * 2 + dir) * UU * BB;
            hw[uF * BB + bF] = hF;
            __threadfence();          // drain h-state store (writers only)
        }
        __syncthreads();

        // per-direction grid barrier: atomic arrive, volatile-load poll
        if (tid == 0) {
            atomicAdd(bar, 1u);
            unsigned int target = (unsigned int)(step + 1) * RBLK;
            while (*(volatile unsigned int*)bar < target) { }
        }
        __syncthreads();

        // off-critical-path: output trace store (read only after kernel ends)
        if (tid < 128)
            g_hout[((size_t)dir * MM + (size_t)bF * TT + t) * UU + uF] = hF;
    }
}

// ---------------------------------------------------------------
// Final FC: out[row] = [h_fwd(row) ; h_bwd(row)] @ fc_W + fc_b
// ---------------------------------------------------------------
__global__ void __launch_bounds__(256)
fc_kernel(const float* __restrict__ fcW, const float* __restrict__ fcb,
          float* __restrict__ out)
{
    int gwarp = (blockIdx.x * 256 + threadIdx.x) >> 5;
    int lane  = threadIdx.x & 31;
    const float* hf = g_hout + (size_t)gwarp * UU;
    const float* hb = g_hout + (size_t)MM * UU + (size_t)gwarp * UU;
    float s0 = 0.f, s1 = 0.f, s2 = 0.f;
    for (int u = lane; u < UU; u += 32) {
        float a = hf[u];
        const float* w = fcW + u * NT;
        s0 += a * w[0]; s1 += a * w[1]; s2 += a * w[2];
        float b = hb[u];
        const float* w2 = fcW + (UU + u) * NT;
        s0 += b * w2[0]; s1 += b * w2[1]; s2 += b * w2[2];
    }
    #pragma unroll
    for (int off = 16; off > 0; off >>= 1) {
        s0 += __shfl_down_sync(0xFFFFFFFFu, s0, off);
        s1 += __shfl_down_sync(0xFFFFFFFFu, s1, off);
        s2 += __shfl_down_sync(0xFFFFFFFFu, s2, off);
    }
    if (lane == 0) {
        out[(size_t)gwarp * NT + 0] = s0 + fcb[0];
        out[(size_t)gwarp * NT + 1] = s1 + fcb[1];
        out[(size_t)gwarp * NT + 2] = s2 + fcb[2];
    }
}

// ---------------------------------------------------------------
extern "C" void kernel_launch(void* const* d_in, const int* in_sizes, int n_in,
                              void* d_out, int out_size)
{
    const int*   tokens = (const int*)  d_in[0];
    const int*   seqlen = (const int*)  d_in[1];
    const float* emb    = (const float*)d_in[2];
    const float* Wkf    = (const float*)d_in[3];
    const float* Wrf    = (const float*)d_in[4];
    const float* bf     = (const float*)d_in[5];
    const float* Wkb    = (const float*)d_in[6];
    const float* Wrb    = (const float*)d_in[7];
    const float* bb     = (const float*)d_in[8];
    const float* fcW    = (const float*)d_in[9];
    const float* fcb    = (const float*)d_in[10];
    float* out = (float*)d_out;

    const int smem_bytes = (DPAD * 16 + DPAD * 32 + 4096 + 512) * 4;  // 76,800 B
    cudaFuncSetAttribute(lstm_rec, cudaFuncAttributeMaxDynamicSharedMemorySize,
                         smem_bytes);

    init_kernel<<<32, 256>>>();
    zx_gemm<<<dim3((NTOT + GBN - 1) / GBN, MM / GBM), 256>>>(tokens, emb, Wkf, Wkb, bf, bb);
    lstm_rec<<<2 * RBLK, RTHREADS, smem_bytes>>>(Wrf, Wrb, seqlen);
    fc_kernel<<<MM / 8, 256>>>(fcW, fcb, out);
}

// round 6
// speedup vs baseline: 1.0569x; 1.0569x over previous
#include <cuda_runtime.h>
#include <cuda_bf16.h>
#include <math.h>

// Problem constants
#define BB 32
#define TT 512
#define DD 300
#define UU 300
#define ZZ 1200               // 4*U
#define MM (BB*TT)            // 16384
#define NTOT (2*ZZ)           // 2400
#define NT 3                  // output classes

// Recurrent kernel partition: 60 blocks/dir x 5 units -> 120 blocks total
// (<=148 SMs: exactly one CTA per SM, no co-residency stragglers)
#define RBLK 60               // blocks per direction
#define RUNITS 5              // units per block (60*5 = 300)
#define RTHREADS 384          // 12 warps -> 3 per SMSP (balanced FFMA)
#define NSLICE 12             // d-slices (one per warp)
#define DCHUNK 25             // d per slice (12*25 = 300 exact)
#define GU 20                 // gates*units per block (4*5)
#define REDSTRIDE 21          // padded stride (conflict-free)
#define REDSLICE (BB*REDSTRIDE)  // 672 floats per slice

// -------- persistent device scratch (no allocations allowed) --------
__device__ float g_zx[(size_t)2 * MM * ZZ];      // [dir][row(b*T+t)][z]
__device__ float g_hout[(size_t)2 * MM * UU];    // [dir][row][u]
__device__ float g_hstate[4 * UU * BB];          // [parity][dir][u*32+b]
__device__ unsigned int g_bar[2];

// ---------------------------------------------------------------
__global__ void init_kernel() {
    int i = blockIdx.x * blockDim.x + threadIdx.x;
    if (i < 2) g_bar[i] = 0u;
    for (int j = i; j < 4 * UU * BB; j += gridDim.x * blockDim.x)
        g_hstate[j] = 0.0f;
}

// ---------------------------------------------------------------
// zx GEMM: zx[dir][b*T+t][z] = emb[inputs[b,t]] @ Wk_dir + b_dir
// 128x128x8 tile, 256 threads, 8x8 register tile, double-buffered
// ---------------------------------------------------------------
#define GBM 128
#define GBN 128
#define GBK 8

__global__ void __launch_bounds__(256)
zx_gemm(const int* __restrict__ tokens,
        const float* __restrict__ emb,
        const float* __restrict__ Wkf, const float* __restrict__ Wkb,
        const float* __restrict__ bf,  const float* __restrict__ bb)
{
    __shared__ float As[GBK][GBM];
    __shared__ float Bs[GBK][GBN];

    const int tid = threadIdx.x;
    const int m0 = blockIdx.y * GBM;
    const int n0 = blockIdx.x * GBN;

    const int a_row = tid >> 1;             // 0..127
    const int a_kq  = (tid & 1) * 4;        // 0 or 4
    const int token = tokens[m0 + a_row];
    const float* arow = emb + (size_t)token * DD;

    const int b_k = tid >> 5;               // 0..7
    const int b_n = (tid & 31) * 4;         // 0..124
    const int ng  = n0 + b_n;
    const int bdir = (ng >= ZZ) ? 1 : 0;
    const float* Wk = bdir ? Wkb : Wkf;
    const int ncol = ng - bdir * ZZ;
    const bool nvalid = (ng < NTOT);

    const int tx = tid & 15;
    const int ty = tid >> 4;

    float acc[8][8];
    #pragma unroll
    for (int i = 0; i < 8; ++i)
        #pragma unroll
        for (int j = 0; j < 8; ++j) acc[i][j] = 0.0f;

    // prefetch tile k0 = 0
    float4 av = make_float4(0.f, 0.f, 0.f, 0.f);
    if (a_kq + 3 < DD) av = *(const float4*)(arow + a_kq);
    float4 bv = make_float4(0.f, 0.f, 0.f, 0.f);
    if (b_k < DD && nvalid) bv = *(const float4*)(Wk + (size_t)b_k * ZZ + ncol);

    for (int k0 = 0; k0 < DD; k0 += GBK) {
        As[a_kq + 0][a_row] = av.x;
        As[a_kq + 1][a_row] = av.y;
        As[a_kq + 2][a_row] = av.z;
        As[a_kq + 3][a_row] = av.w;
        *(float4*)&Bs[b_k][b_n] = bv;
        __syncthreads();

        int kn = k0 + GBK;
        av = make_float4(0.f, 0.f, 0.f, 0.f);
        bv = make_float4(0.f, 0.f, 0.f, 0.f);
        if (kn < DD) {
            int k = kn + a_kq;
            if (k + 3 < DD) av = *(const float4*)(arow + k);
            int kb = kn + b_k;
            if (kb < DD && nvalid)
                bv = *(const float4*)(Wk + (size_t)kb * ZZ + ncol);
        }

        #pragma unroll
        for (int kk = 0; kk < GBK; ++kk) {
            float4 a0 = *(float4*)&As[kk][ty * 8];
            float4 a1 = *(float4*)&As[kk][ty * 8 + 4];
            float4 b0 = *(float4*)&Bs[kk][tx * 8];
            float4 b1 = *(float4*)&Bs[kk][tx * 8 + 4];
            float af[8] = {a0.x, a0.y, a0.z, a0.w, a1.x, a1.y, a1.z, a1.w};
            float bfr[8] = {b0.x, b0.y, b0.z, b0.w, b1.x, b1.y, b1.z, b1.w};
            #pragma unroll
            for (int i = 0; i < 8; ++i)
                #pragma unroll
                for (int j = 0; j < 8; ++j)
                    acc[i][j] += af[i] * bfr[j];
        }
        __syncthreads();
    }

    #pragma unroll
    for (int i = 0; i < 8; ++i) {
        int m = m0 + ty * 8 + i;
        #pragma unroll
        for (int j = 0; j < 8; ++j) {
            int n = n0 + tx * 8 + j;
            if (n < NTOT) {
                int dir = (n >= ZZ) ? 1 : 0;
                int zc = n - dir * ZZ;
                float bias = dir ? bb[zc] : bf[zc];
                g_zx[(size_t)dir * MM * ZZ + (size_t)m * ZZ + zc] = acc[i][j] + bias;
            }
        }
    }
}

// ---------------------------------------------------------------
// Persistent recurrent kernel. 120 blocks (60/dir), 384 threads,
// one CTA per SM. Each block: 5 units x 4 gates x 32 batches.
// Thread map: warp = d-slice (12 slices x 25 d), lane = batch.
// Each thread: acc[20] (all gate-units) for its batch over its slice.
// Wr in SMEM (LDS broadcast). zx prefetched one step ahead into regs.
// h exchanged via double-buffered global state + per-dir barrier
// (atomic arrive, volatile-load poll, writer-only fence).
// ---------------------------------------------------------------
__device__ __forceinline__ float sigf(float x) {
    return 1.0f / (1.0f + __expf(-x));
}

__global__ void __launch_bounds__(RTHREADS, 1)
lstm_rec(const float* __restrict__ Wrf, const float* __restrict__ Wrb,
         const int* __restrict__ seqlen)
{
    extern __shared__ float smem[];
    float* w_sh = smem;                          // DD*GU   = 6000 [d][g*5+u]
    float* h_sh = smem + DD * GU;                // DD*BB   = 9600 [d][b]
    float* red  = smem + DD * GU + DD * BB;      // 12*672  = 8064

    const int tid  = threadIdx.x;
    const int dir  = blockIdx.x / RBLK;
    const int blk  = blockIdx.x % RBLK;
    const int u0   = blk * RUNITS;

    const float* Wr  = dir ? Wrb : Wrf;
    const float* zxd = g_zx + (size_t)dir * MM * ZZ;

    // fill Wr slice once: w_sh[d*20 + g*5+u] = Wr[d][g*300 + u0+u]
    for (int i = tid; i < DD * GU; i += RTHREADS) {
        int d  = i / GU;
        int gu = i % GU;
        int g  = gu / RUNITS;
        int uu = gu % RUNITS;
        w_sh[i] = Wr[(size_t)d * ZZ + g * UU + u0 + uu];
    }

    const int ds   = tid >> 5;      // d-slice 0..11 (warp id)
    const int lane = tid & 31;      // batch

    // finisher threads (tid < 160): one (u,b) cell each
    float cF = 0.0f, hF = 0.0f;
    int uF = 0, bF = 0, slen = 0;
    if (tid < 160) {
        uF = tid >> 5;              // local unit 0..4
        bF = lane;
        slen = seqlen[bF];
    }
    __syncthreads();

    unsigned int* bar = &g_bar[dir];
    const float4* w4 = (const float4*)w_sh;

    // prefetch first step's zx (registers)
    float zxr[4] = {0.f, 0.f, 0.f, 0.f};
    {
        int t0 = dir ? (TT - 1) : 0;
        if (tid < 160) {
            #pragma unroll
            for (int g = 0; g < 4; ++g)
                zxr[g] = zxd[((size_t)bF * TT + t0) * ZZ + g * UU + u0 + uF];
        }
    }

    for (int step = 0; step < TT; ++step) {
        const int t = dir ? (TT - 1 - step) : step;

        // reload h first (critical path) — bypass L1
        {
            const float4* hin =
                (const float4*)(g_hstate + ((step & 1) * 2 + dir) * UU * BB);
            float4* hsh4 = (float4*)h_sh;
            for (int i = tid; i < (UU * BB) / 4; i += RTHREADS)
                hsh4[i] = __ldcg(hin + i);
        }

        // prefetch NEXT step's zx into regs (consumed next iteration)
        float zxn[4] = {0.f, 0.f, 0.f, 0.f};
        if (step + 1 < TT && tid < 160) {
            int tn = dir ? (TT - 2 - step) : (step + 1);
            #pragma unroll
            for (int g = 0; g < 4; ++g)
                zxn[g] = zxd[((size_t)bF * TT + tn) * ZZ + g * UU + u0 + uF];
        }
        __syncthreads();

        // partial dots: this warp's 25-d slice, all 20 gate-units, my batch
        float acc[GU];
        #pragma unroll
        for (int k = 0; k < GU; ++k) acc[k] = 0.0f;

        #pragma unroll
        for (int it = 0; it < DCHUNK; ++it) {
            int d = ds * DCHUNK + it;
            float hb = h_sh[d * BB + lane];
            #pragma unroll
            for (int q = 0; q < 5; ++q) {
                float4 w = w4[d * 5 + q];
                acc[4 * q + 0] += w.x * hb;
                acc[4 * q + 1] += w.y * hb;
                acc[4 * q + 2] += w.z * hb;
                acc[4 * q + 3] += w.w * hb;
            }
        }

        // spill partials (padded stride, conflict-free)
        {
            float* rr = red + ds * REDSLICE + lane * REDSTRIDE;
            #pragma unroll
            for (int k = 0; k < GU; ++k) rr[k] = acc[k];
        }
        __syncthreads();

        // finish: reduce 12 slices, gates, state update, store h-state
        if (tid < 160) {
            float zg[4];
            #pragma unroll
            for (int g = 0; g < 4; ++g) zg[g] = zxr[g];
            #pragma unroll
            for (int s = 0; s < NSLICE; ++s) {
                const float* rr = red + s * REDSLICE + bF * REDSTRIDE;
                zg[0] += rr[0 * RUNITS + uF];
                zg[1] += rr[1 * RUNITS + uF];
                zg[2] += rr[2 * RUNITS + uF];
                zg[3] += rr[3 * RUNITS + uF];
            }
            float ig = sigf(zg[0]);
            float fg = sigf(zg[1]);
            float gg = tanhf(zg[2]);
            float og = sigf(zg[3]);
            float cn = fg * cF + ig * gg;
            float hn = og * tanhf(cn);
            if (t < slen) { cF = cn; hF = hn; }
            float* hw = g_hstate + (((step + 1) & 1) * 2 + dir) * UU * BB;
            hw[(u0 + uF) * BB + bF] = hF;                       // coalesced
            g_hout[((size_t)dir * MM + (size_t)bF * TT + t) * UU + u0 + uF] = hF;
            __threadfence();        // writer-only drain of h-state store
        }
        __syncthreads();

        // per-direction grid barrier: atomic arrive, volatile-load poll
        if (tid == 0) {
            atomicAdd(bar, 1u);
            unsigned int target = (unsigned int)(step + 1) * RBLK;
            while (*(volatile unsigned int*)bar < target) { }
        }
        __syncthreads();

        #pragma unroll
        for (int g = 0; g < 4; ++g) zxr[g] = zxn[g];
    }
}

// ---------------------------------------------------------------
// Final FC: out[row] = [h_fwd(row) ; h_bwd(row)] @ fc_W + fc_b
// ---------------------------------------------------------------
__global__ void __launch_bounds__(256)
fc_kernel(const float* __restrict__ fcW, const float* __restrict__ fcb,
          float* __restrict__ out)
{
    int gwarp = (blockIdx.x * 256 + threadIdx.x) >> 5;
    int lane  = threadIdx.x & 31;
    const float* hf = g_hout + (size_t)gwarp * UU;
    const float* hb = g_hout + (size_t)MM * UU + (size_t)gwarp * UU;
    float s0 = 0.f, s1 = 0.f, s2 = 0.f;
    for (int u = lane; u < UU; u += 32) {
        float a = hf[u];
        const float* w = fcW + u * NT;
        s0 += a * w[0]; s1 += a * w[1]; s2 += a * w[2];
        float b = hb[u];
        const float* w2 = fcW + (UU + u) * NT;
        s0 += b * w2[0]; s1 += b * w2[1]; s2 += b * w2[2];
    }
    #pragma unroll
    for (int off = 16; off > 0; off >>= 1) {
        s0 += __shfl_down_sync(0xFFFFFFFFu, s0, off);
        s1 += __shfl_down_sync(0xFFFFFFFFu, s1, off);
        s2 += __shfl_down_sync(0xFFFFFFFFu, s2, off);
    }
    if (lane == 0) {
        out[(size_t)gwarp * NT + 0] = s0 + fcb[0];
        out[(size_t)gwarp * NT + 1] = s1 + fcb[1];
        out[(size_t)gwarp * NT + 2] = s2 + fcb[2];
    }
}

// ---------------------------------------------------------------
extern "C" void kernel_launch(void* const* d_in, const int* in_sizes, int n_in,
                              void* d_out, int out_size)
{
    const int*   tokens = (const int*)  d_in[0];
    const int*   seqlen = (const int*)  d_in[1];
    const float* emb    = (const float*)d_in[2];
    const float* Wkf    = (const float*)d_in[3];
    const float* Wrf    = (const float*)d_in[4];
    const float* bf     = (const float*)d_in[5];
    const float* Wkb    = (const float*)d_in[6];
    const float* Wrb    = (const float*)d_in[7];
    const float* bb     = (const float*)d_in[8];
    const float* fcW    = (const float*)d_in[9];
    const float* fcb    = (const float*)d_in[10];
    float* out = (float*)d_out;

    const int smem_bytes = (DD * GU + DD * BB + NSLICE * REDSLICE) * 4; // 94,656 B
    cudaFuncSetAttribute(lstm_rec, cudaFuncAttributeMaxDynamicSharedMemorySize,
                         smem_bytes);

    init_kernel<<<32, 256>>>();
    zx_gemm<<<dim3((NTOT + GBN - 1) / GBN, MM / GBM), 256>>>(tokens, emb, Wkf, Wkb, bf, bb);
    lstm_rec<<<2 * RBLK, RTHREADS, smem_bytes>>>(Wrf, Wrb, seqlen);
    fc_kernel<<<MM / 8, 256>>>(fcW, fcb, out);
}